// round 16
// baseline (speedup 1.0000x reference)
#include <cuda_runtime.h>
#include <cstdint>

// XingLoss on GB300 (sm_103a) — FINAL kernel (converged, 15 rounds).
//
// Fixed geometry: x_list (P=16384, N=1024, 2) float32, scale scalar.
// segn = N/4 = 256 segments per row; segment i uses points 3i..3i+3
// -> touched floats per row: [0, 1538); the reference's wrap-concat is dead.
//
// Converged design (every piece measured against alternatives):
//  - grid 2048 x 256, 8 rows/block, 32 regs -> 8 resident blocks/SM
//  - stride-3 LDG.64 loads: four alternative load shapes (incl. zero-
//    redundancy LDG.128 + shuffle) all tie -> DRAM unique-byte bound at
//    ~6.1 TB/s wall on 102.8 MB of touched lines
//  - algebraic cut: direct = (s12>=0) reduces to sign(cross(v1,v2)) since
//    the norm product is positive -> one rsqrt per segment, no division
//  - barrier-free exit: thread 0 adds the block sum to 1-of-32 spread L2
//    slots (contention-free), bumps a counter; the last-arriving block
//    folds the 32 slots, applies scale/(segn*P), writes the scalar, and
//    resets all device state so CUDA-graph replays are deterministic.
#define N_POINTS        1024
#define SEGN            256
#define ROWS_PER_BLOCK  8
#define NSLOTS          32

__device__ float        g_slots[NSLOTS];   // zero-init at load; reset each launch
__device__ unsigned int g_counter = 0;

// Crossing term for one segment given its 4 points.
__device__ __forceinline__ float seg_term(float2 p0, float2 p1, float2 p2, float2 p3)
{
    const float v1x = p1.x - p0.x, v1y = p1.y - p0.y;
    const float v2x = p2.x - p1.x, v2y = p2.y - p1.y;
    const float v3x = p3.x - p2.x, v3y = p3.y - p2.y;

    const float c12 = v1x * v2y - v1y * v2x;
    const float c13 = v1x * v3y - v1y * v3x;

    const float n2   = (v1x * v1x + v1y * v1y) * (v3x * v3x + v3y * v3y);
    const float sina = c13 * rsqrtf(n2);

    return (c12 >= 0.0f) ? fmaxf(-sina, 0.0f) : fmaxf(sina, 0.0f);
}

__global__ void __launch_bounds__(SEGN, 8) xing_kernel(
    const float* __restrict__ x,
    const uint32_t* __restrict__ scale_raw,
    float* __restrict__ out, int P, int nblocks)
{
    const int t = threadIdx.x;               // segment index 0..255

    // Segment t starts at point 3t within each row.
    const float2* __restrict__ base =
        reinterpret_cast<const float2*>(x)
        + (size_t)blockIdx.x * ROWS_PER_BLOCK * N_POINTS + 3 * t;

    float acc = 0.0f;

    #pragma unroll
    for (int r = 0; r < ROWS_PER_BLOCK; r++) {
        const float2* p = base + (size_t)r * N_POINTS;
        const float2 p0 = __ldg(p + 0);
        const float2 p1 = __ldg(p + 1);
        const float2 p2 = __ldg(p + 2);
        const float2 p3 = __ldg(p + 3);
        acc += seg_term(p0, p1, p2, p3);
    }

    // ---- block reduce ----
    #pragma unroll
    for (int o = 16; o > 0; o >>= 1)
        acc += __shfl_down_sync(0xFFFFFFFFu, acc, o);

    __shared__ float s[SEGN / 32];
    if ((t & 31) == 0) s[t >> 5] = acc;
    __syncthreads();

    // Thread 0 only: accumulate into spread slots, detect last block, finalize.
    // Other threads (and other blocks) exit immediately — no extra barrier.
    if (t == 0) {
        float bs = 0.0f;
        #pragma unroll
        for (int i = 0; i < SEGN / 32; i++) bs += s[i];

        // 32 distinct L2 addresses, ~64 adds each, spread over the kernel
        // lifetime -> negligible atomic contention.
        atomicAdd(&g_slots[blockIdx.x & (NSLOTS - 1)], bs);
        __threadfence();
        unsigned int done = atomicAdd(&g_counter, 1u);

        if (done == (unsigned int)(nblocks - 1)) {
            // Last block: fold the 32 slots (32 independent loads, one
            // latency exposure) and reset state for the next graph replay.
            float v[NSLOTS];
            #pragma unroll
            for (int i = 0; i < NSLOTS; i++) v[i] = __ldcg(&g_slots[i]);

            float total = 0.0f;
            #pragma unroll
            for (int i = 0; i < NSLOTS; i++) {
                total += v[i];
                g_slots[i] = 0.0f;
            }

            // Decode scale: float32 bit pattern vs integer bit pattern.
            uint32_t u = scale_raw[0];
            float    f = __uint_as_float(u);
            float    scale;
            if (fabsf(f) >= 1e-30f && fabsf(f) < 1e30f) scale = f;
            else                                        scale = (float)(int)u;

            out[0] = total * scale / ((float)SEGN * (float)P);
            atomicExch(&g_counter, 0u);       // reset for next replay
        }
    }
}

extern "C" void kernel_launch(void* const* d_in, const int* in_sizes, int n_in,
                              void* d_out, int out_size)
{
    const float*    x     = (const float*)d_in[0];
    const uint32_t* scale = (const uint32_t*)d_in[1];
    float*          out   = (float*)d_out;

    int P       = in_sizes[0] / (N_POINTS * 2);     // 16384
    int nblocks = P / ROWS_PER_BLOCK;               // 2048

    xing_kernel<<<nblocks, SEGN>>>(x, scale, out, P, nblocks);
}

// round 17
// speedup vs baseline: 1.0133x; 1.0133x over previous
#include <cuda_runtime.h>
#include <cstdint>

// XingLoss on GB300 (sm_103a) — FINAL kernel (converged over 16 rounds).
//
// Fixed geometry: x_list (P=16384, N=1024, 2) float32, scale scalar.
// segn = N/4 = 256 segments per row; segment i uses points 3i..3i+3
// -> touched floats per row: [0, 1538); the reference's wrap-concat is dead.
//
// Converged design (every piece measured against alternatives):
//  - grid 2048 x 256, 8 rows/block, 32 regs -> 8 resident blocks/SM
//    (2048-thread/SM occupancy ceiling)
//  - stride-3 LDG.64 loads: four load shapes (incl. zero-redundancy
//    LDG.128 + shuffle) all tie -> the kernel is bound by unique DRAM
//    line traffic (102.8 MB) at ~6.1 TB/s wall, ~96% of the measured
//    path-independent LTS/DRAM cap
//  - algebraic cut: direct = (s12>=0) reduces to sign(cross(v1,v2)) since
//    the norm product is positive -> one rsqrt per segment, no division
//  - barrier-free exit: thread 0 adds the block sum to 1-of-32 spread L2
//    slots (contention-free), bumps a counter; the last-arriving block
//    folds the 32 slots, applies scale/(segn*P), writes the scalar, and
//    resets all device state so CUDA-graph replays are deterministic.
#define N_POINTS        1024
#define SEGN            256
#define ROWS_PER_BLOCK  8
#define NSLOTS          32

__device__ float        g_slots[NSLOTS];   // zero-init at load; reset each launch
__device__ unsigned int g_counter = 0;

// Crossing term for one segment given its 4 points.
__device__ __forceinline__ float seg_term(float2 p0, float2 p1, float2 p2, float2 p3)
{
    const float v1x = p1.x - p0.x, v1y = p1.y - p0.y;
    const float v2x = p2.x - p1.x, v2y = p2.y - p1.y;
    const float v3x = p3.x - p2.x, v3y = p3.y - p2.y;

    const float c12 = v1x * v2y - v1y * v2x;
    const float c13 = v1x * v3y - v1y * v3x;

    const float n2   = (v1x * v1x + v1y * v1y) * (v3x * v3x + v3y * v3y);
    const float sina = c13 * rsqrtf(n2);

    return (c12 >= 0.0f) ? fmaxf(-sina, 0.0f) : fmaxf(sina, 0.0f);
}

__global__ void __launch_bounds__(SEGN, 8) xing_kernel(
    const float* __restrict__ x,
    const uint32_t* __restrict__ scale_raw,
    float* __restrict__ out, int P, int nblocks)
{
    const int t = threadIdx.x;               // segment index 0..255

    // Segment t starts at point 3t within each row.
    const float2* __restrict__ base =
        reinterpret_cast<const float2*>(x)
        + (size_t)blockIdx.x * ROWS_PER_BLOCK * N_POINTS + 3 * t;

    float acc = 0.0f;

    #pragma unroll
    for (int r = 0; r < ROWS_PER_BLOCK; r++) {
        const float2* p = base + (size_t)r * N_POINTS;
        const float2 p0 = __ldg(p + 0);
        const float2 p1 = __ldg(p + 1);
        const float2 p2 = __ldg(p + 2);
        const float2 p3 = __ldg(p + 3);
        acc += seg_term(p0, p1, p2, p3);
    }

    // ---- block reduce ----
    #pragma unroll
    for (int o = 16; o > 0; o >>= 1)
        acc += __shfl_down_sync(0xFFFFFFFFu, acc, o);

    __shared__ float s[SEGN / 32];
    if ((t & 31) == 0) s[t >> 5] = acc;
    __syncthreads();

    // Thread 0 only: accumulate into spread slots, detect last block, finalize.
    // Other threads (and other blocks) exit immediately — no extra barrier.
    if (t == 0) {
        float bs = 0.0f;
        #pragma unroll
        for (int i = 0; i < SEGN / 32; i++) bs += s[i];

        // 32 distinct L2 addresses, ~64 adds each, spread over the kernel
        // lifetime -> negligible atomic contention.
        atomicAdd(&g_slots[blockIdx.x & (NSLOTS - 1)], bs);
        __threadfence();
        unsigned int done = atomicAdd(&g_counter, 1u);

        if (done == (unsigned int)(nblocks - 1)) {
            // Last block: fold the 32 slots (32 independent loads, one
            // latency exposure) and reset state for the next graph replay.
            float v[NSLOTS];
            #pragma unroll
            for (int i = 0; i < NSLOTS; i++) v[i] = __ldcg(&g_slots[i]);

            float total = 0.0f;
            #pragma unroll
            for (int i = 0; i < NSLOTS; i++) {
                total += v[i];
                g_slots[i] = 0.0f;
            }

            // Decode scale: float32 bit pattern vs integer bit pattern.
            uint32_t u = scale_raw[0];
            float    f = __uint_as_float(u);
            float    scale;
            if (fabsf(f) >= 1e-30f && fabsf(f) < 1e30f) scale = f;
            else                                        scale = (float)(int)u;

            out[0] = total * scale / ((float)SEGN * (float)P);
            atomicExch(&g_counter, 0u);       // reset for next replay
        }
    }
}

extern "C" void kernel_launch(void* const* d_in, const int* in_sizes, int n_in,
                              void* d_out, int out_size)
{
    const float*    x     = (const float*)d_in[0];
    const uint32_t* scale = (const uint32_t*)d_in[1];
    float*          out   = (float*)d_out;

    int P       = in_sizes[0] / (N_POINTS * 2);     // 16384
    int nblocks = P / ROWS_PER_BLOCK;               // 2048

    xing_kernel<<<nblocks, SEGN>>>(x, scale, out, P, nblocks);
}